// round 14
// baseline (speedup 1.0000x reference)
#include <cuda_runtime.h>
#include <cuda_fp16.h>
#include <cstdint>

#define Bb 4
#define Nn 10000
#define Ee 160000
#define Mm 4
#define Hh 64
#define OUTd 64
#define Ff 64

#define ROWS (Bb*Nn*Mm)      /* 160000 projected rows, each 128 -> 64 */
#define EDGES (Bb*Ee)        /* 640000 */
#define NODES (Bb*Nn)        /* 40000 target buckets */

// Scratch (allocation-free rule: __device__ globals)
__device__ __half             g_nh[(size_t)ROWS * OUTd];  // 20.5 MB projected (fp16)
__device__ int                g_count[NODES];             // histogram by (b,tgt)
__device__ int                g_beg[NODES];               // segment start
__device__ int                g_pos[NODES];               // fill cursors
__device__ unsigned long long g_rec[EDGES];               // packed {src, coeff}
__device__ int                g_cursor;                   // allocator cursor

// ---------------------------------------------------------------------------
// Side stream + fork/join events (created at load; not device allocations)
// ---------------------------------------------------------------------------
static cudaStream_t s_side;
static cudaEvent_t  ev_fork, ev_join;
static struct SideInit {
    SideInit() {
        cudaStreamCreateWithFlags(&s_side, cudaStreamNonBlocking);
        cudaEventCreateWithFlags(&ev_fork, cudaEventDisableTiming);
        cudaEventCreateWithFlags(&ev_join, cudaEventDisableTiming);
    }
} s_side_init;

// ---------------------------------------------------------------------------
// Kernel 0: zero histogram + allocator cursor
// ---------------------------------------------------------------------------
__global__ void k_zero()
{
    int i = blockIdx.x * blockDim.x + threadIdx.x;
    if (i < NODES) g_count[i] = 0;
    if (i == 0) g_cursor = 0;
}

// ---------------------------------------------------------------------------
// Kernel 1: target histogram (only needs idx)
// ---------------------------------------------------------------------------
__global__ __launch_bounds__(256)
void k_hist(const int* __restrict__ idx)
{
    int e = blockIdx.x * blockDim.x + threadIdx.x;
    if (e >= EDGES) return;
    int b   = e / Ee;
    int tgt = idx[(size_t)e * 2 + 1];
    atomicAdd(&g_count[b * Nn + tgt], 1);
}

// ---------------------------------------------------------------------------
// Kernel 2: warp-aggregated segment allocation
// ---------------------------------------------------------------------------
__global__ __launch_bounds__(256)
void k_alloc()
{
    int n    = blockIdx.x * blockDim.x + threadIdx.x;
    int lane = threadIdx.x & 31;

    int c = (n < NODES) ? g_count[n] : 0;

    int s = c;
    #pragma unroll
    for (int off = 1; off < 32; off <<= 1) {
        int v = __shfl_up_sync(0xFFFFFFFFu, s, off);
        if (lane >= off) s += v;
    }
    int total = __shfl_sync(0xFFFFFFFFu, s, 31);

    int base = 0;
    if (lane == 31) base = atomicAdd(&g_cursor, total);
    base = __shfl_sync(0xFFFFFFFFu, base, 31);

    if (n < NODES) {
        int beg = base + s - c;
        g_beg[n] = beg;
        g_pos[n] = beg;
    }
}

// ---------------------------------------------------------------------------
// Kernel 3: projection (side stream). 8 rows x 4 cols per thread, 128-row
// tile; X tile stored fp16 in smem -> 65KB total -> 3 CTA/SM (24 warps).
// ---------------------------------------------------------------------------
#define PROJ_ROWS_PER_BLK 128
#define PROJ_BLOCKS (ROWS / PROJ_ROWS_PER_BLK)   /* 1250 */
#define XPITCH2 132                              /* halves per row (128 + 4 pad) */
#define PROJ_SMEM_BYTES (128*64*4 + PROJ_ROWS_PER_BLK*XPITCH2*2)  /* 66560 */

__global__ __launch_bounds__(256, 3)
void k_project(const float* __restrict__ node,
               const float* __restrict__ hidden,
               const float* __restrict__ Wnh,
               const float* __restrict__ bnh)
{
    extern __shared__ float sm[];
    float*  Ws  = sm;                               // [128][64] fp32
    __half* Xsh = (__half*)(sm + 128 * 64);         // [128][XPITCH2] fp16

    const int tid  = threadIdx.x;
    const int row0 = blockIdx.x * PROJ_ROWS_PER_BLK;

    #pragma unroll
    for (int i = tid; i < 128 * 64; i += 256) Ws[i] = Wnh[i];

    // X tile: per iter load one float4, convert to 2x half2, store 8 bytes
    const float4* node4   = (const float4*)node;
    const float4* hidden4 = (const float4*)hidden;
    #pragma unroll
    for (int i = tid; i < PROJ_ROWS_PER_BLK * 32; i += 256) {
        int r = i >> 5;
        int q = i & 31;
        int grow = row0 + r;
        float4 v;
        int col;
        if (q < 16) { v = __ldg(&node4[(size_t)grow * 16 + q]);          col = q * 4; }
        else        { v = __ldg(&hidden4[(size_t)grow * 16 + (q - 16)]); col = 64 + (q - 16) * 4; }
        __half2 h0 = __floats2half2_rn(v.x, v.y);
        __half2 h1 = __floats2half2_rn(v.z, v.w);
        uint2 pk;
        pk.x = *(unsigned*)&h0;
        pk.y = *(unsigned*)&h1;
        *(uint2*)&Xsh[r * XPITCH2 + col] = pk;      // 8B store, 8B aligned
    }
    __syncthreads();

    const int obase = (tid & 15) * 4;   // 16 col-groups * 4 = 64 outputs
    const int rbase = (tid >> 4) * 8;   // 16 row-groups * 8 = 128 rows

    float4 acc[8];
    {
        float4 b = *(const float4*)&bnh[obase];
        #pragma unroll
        for (int r = 0; r < 8; r++) acc[r] = b;
    }

    #pragma unroll 2
    for (int cb = 0; cb < 128; cb += 4) {
        const float4 w0 = *(const float4*)&Ws[(cb + 0) * 64 + obase];
        const float4 w1 = *(const float4*)&Ws[(cb + 1) * 64 + obase];
        const float4 w2 = *(const float4*)&Ws[(cb + 2) * 64 + obase];
        const float4 w3 = *(const float4*)&Ws[(cb + 3) * 64 + obase];
        #pragma unroll
        for (int r = 0; r < 8; r++) {
            uint2 xr = *(const uint2*)&Xsh[(rbase + r) * XPITCH2 + cb];
            float2 x01 = __half22float2(*(__half2*)&xr.x);
            float2 x23 = __half22float2(*(__half2*)&xr.y);
            acc[r].x += x01.x * w0.x; acc[r].y += x01.x * w0.y; acc[r].z += x01.x * w0.z; acc[r].w += x01.x * w0.w;
            acc[r].x += x01.y * w1.x; acc[r].y += x01.y * w1.y; acc[r].z += x01.y * w1.z; acc[r].w += x01.y * w1.w;
            acc[r].x += x23.x * w2.x; acc[r].y += x23.x * w2.y; acc[r].z += x23.x * w2.z; acc[r].w += x23.x * w2.w;
            acc[r].x += x23.y * w3.x; acc[r].y += x23.y * w3.y; acc[r].z += x23.y * w3.z; acc[r].w += x23.y * w3.w;
        }
    }

    #pragma unroll
    for (int r = 0; r < 8; r++) {
        size_t off = (size_t)(row0 + rbase + r) * 64 + obase;   // half units
        __half2 h0 = __floats2half2_rn(acc[r].x, acc[r].y);
        __half2 h1 = __floats2half2_rn(acc[r].z, acc[r].w);
        uint2 pk;
        pk.x = *(unsigned*)&h0;
        pk.y = *(unsigned*)&h1;
        *(uint2*)(g_nh + off) = pk;
    }
}

// ---------------------------------------------------------------------------
// Kernel 4: per-edge gate + CSR fill. EIGHT edges per warp, float4 loads:
// each half-warp covers one 256B edge row per step (16 lanes x LDG.128),
// 4 independent steps in flight, xor-reduce within 16-lane groups.
// ---------------------------------------------------------------------------
__global__ __launch_bounds__(256)
void k_coeff_fill(const float* __restrict__ ef,
                  const float* __restrict__ We,
                  const float* __restrict__ be,
                  const int*   __restrict__ idx)
{
    int wq   = (blockIdx.x * blockDim.x + threadIdx.x) >> 5;   // warp id
    int lane = threadIdx.x & 31;
    int e0   = wq * 8;
    if (e0 >= EDGES) return;

    int half = lane >> 4;          // 0 or 1
    int l15  = lane & 15;

    const float4* ef4 = (const float4*)ef;
    float4 w4 = __ldg((const float4*)We + l15);

    float acc[4];
    #pragma unroll
    for (int s = 0; s < 4; s++) {
        // edge for this half-warp at this step
        int e = e0 + 2 * s + half;
        float4 x = __ldg(&ef4[(size_t)e * 16 + l15]);   // 16B of the 256B row
        acc[s] = x.x * w4.x + x.y * w4.y + x.z * w4.z + x.w * w4.w;
    }

    // reduce within each 16-lane group (xor 8,4,2,1 stays inside the group)
    #pragma unroll
    for (int off = 8; off > 0; off >>= 1) {
        acc[0] += __shfl_xor_sync(0xFFFFFFFFu, acc[0], off);
        acc[1] += __shfl_xor_sync(0xFFFFFFFFu, acc[1], off);
        acc[2] += __shfl_xor_sync(0xFFFFFFFFu, acc[2], off);
        acc[3] += __shfl_xor_sync(0xFFFFFFFFu, acc[3], off);
    }

    if (l15 == 0) {
        float bias = __ldg(&be[0]);
        #pragma unroll
        for (int s = 0; s < 4; s++) {
            int e = e0 + 2 * s + half;
            float cf = acc[s] + bias;
            int2 st  = __ldg((const int2*)idx + e);      // {src, tgt}
            int  b   = e / Ee;
            int  p   = atomicAdd(&g_pos[b * Nn + st.y], 1);
            unsigned long long rec =
                (unsigned long long)(unsigned)st.x |
                ((unsigned long long)__float_as_uint(cf) << 32);
            g_rec[p] = rec;
        }
    }
}

// ---------------------------------------------------------------------------
// Kernel 5: accumulate (fp16 gather). One warp per node. Per edge a single
// LDG.128 gathers 8 halves/lane (512 B/warp); fp32 accumulation.
// ---------------------------------------------------------------------------
__global__ __launch_bounds__(256)
void k_accum(float* __restrict__ out)
{
    int n    = (blockIdx.x * blockDim.x + threadIdx.x) >> 5;
    int lane = threadIdx.x & 31;
    if (n >= NODES) return;

    int beg = g_beg[n];
    int cnt = g_count[n];
    int b   = n / Nn;

    const __half* basep = g_nh + (size_t)b * Nn * 256;

    float a[8];
    #pragma unroll
    for (int i = 0; i < 8; i++) a[i] = 0.f;

    for (int c0 = 0; c0 < cnt; c0 += 32) {
        int m = cnt - c0; if (m > 32) m = 32;
        unsigned long long rec = 0;
        if (lane < m) rec = __ldcs(&g_rec[beg + c0 + lane]);   // streaming
        int   rsrc = (int)(unsigned)(rec & 0xFFFFFFFFull);
        float rcf  = __uint_as_float((unsigned)(rec >> 32));

        #pragma unroll 8
        for (int k = 0; k < m; k++) {
            int   sidx = __shfl_sync(0xFFFFFFFFu, rsrc, k);
            float cf   = __shfl_sync(0xFFFFFFFFu, rcf,  k);
            const float4* p = (const float4*)(basep + (size_t)sidx * 256);
            float4 raw = __ldg(p + lane);                      // 8 halves
            const __half2* h2 = (const __half2*)&raw;
            float2 f;
            f = __half22float2(h2[0]); a[0] += cf * f.x; a[1] += cf * f.y;
            f = __half22float2(h2[1]); a[2] += cf * f.x; a[3] += cf * f.y;
            f = __half22float2(h2[2]); a[4] += cf * f.x; a[5] += cf * f.y;
            f = __half22float2(h2[3]); a[6] += cf * f.x; a[7] += cf * f.y;
        }
    }

    float* t = out + (size_t)n * 256 + lane * 8;
    __stcs((float4*)t,     make_float4(a[0], a[1], a[2], a[3]));
    __stcs((float4*)t + 1, make_float4(a[4], a[5], a[6], a[7]));
}

// ---------------------------------------------------------------------------
// launch graph (edge chain enqueued FIRST so its blocks win SM slots):
//   stream0: zero -> hist -> alloc -> coeff_fill ┐
//   side:    project (dep: graph entry only)     ├-> accum (stream0)
// inputs: node_fts, hidden, edge_fts, W_nh, b_nh, W_e, b_e, edge_indices(i32)
// ---------------------------------------------------------------------------
extern "C" void kernel_launch(void* const* d_in, const int* in_sizes, int n_in,
                              void* d_out, int out_size)
{
    const float* node   = (const float*)d_in[0];
    const float* hidden = (const float*)d_in[1];
    const float* ef     = (const float*)d_in[2];
    const float* Wnh    = (const float*)d_in[3];
    const float* bnh    = (const float*)d_in[4];
    const float* We     = (const float*)d_in[5];
    const float* be     = (const float*)d_in[6];
    const int*   idx    = (const int*)d_in[7];
    float*       out    = (float*)d_out;

    cudaFuncSetAttribute(k_project, cudaFuncAttributeMaxDynamicSharedMemorySize,
                         PROJ_SMEM_BYTES);

    // fork point at graph entry
    cudaEventRecord(ev_fork, 0);
    cudaStreamWaitEvent(s_side, ev_fork, 0);

    // edge chain on the capture stream (enqueued first)
    k_zero<<<(NODES + 255) / 256, 256>>>();
    k_hist<<<(EDGES + 255) / 256, 256>>>(idx);
    k_alloc<<<(NODES + 255) / 256, 256>>>();
    k_coeff_fill<<<(EDGES / 8 + 7) / 8, 256>>>(ef, We, be, idx);

    // projection on side stream (independent branch)
    k_project<<<PROJ_BLOCKS, 256, PROJ_SMEM_BYTES, s_side>>>(node, hidden, Wnh, bnh);
    cudaEventRecord(ev_join, s_side);

    // join: accum needs both g_nh (project) and the CSR records (edge chain)
    cudaStreamWaitEvent(0, ev_join, 0);
    k_accum<<<(NODES * 32 + 255) / 256, 256>>>(out);
}

// round 15
// speedup vs baseline: 1.0030x; 1.0030x over previous
#include <cuda_runtime.h>
#include <cuda_fp16.h>
#include <cstdint>

#define Bb 4
#define Nn 10000
#define Ee 160000
#define Mm 4
#define Hh 64
#define OUTd 64
#define Ff 64

#define ROWS (Bb*Nn*Mm)      /* 160000 projected rows, each 128 -> 64 */
#define EDGES (Bb*Ee)        /* 640000 */
#define NODES (Bb*Nn)        /* 40000 target buckets */

// Scratch (allocation-free rule: __device__ globals)
__device__ __half             g_nh[(size_t)ROWS * OUTd];  // 20.5 MB projected (fp16)
__device__ int                g_count[NODES];             // histogram by (b,tgt)
__device__ int                g_beg[NODES];               // segment start
__device__ int                g_pos[NODES];               // fill cursors
__device__ unsigned long long g_rec[EDGES];               // packed {src, coeff}
__device__ int                g_cursor;                   // allocator cursor

// ---------------------------------------------------------------------------
// Side stream + fork/join events (created at load; not device allocations)
// ---------------------------------------------------------------------------
static cudaStream_t s_side;
static cudaEvent_t  ev_fork, ev_join;
static struct SideInit {
    SideInit() {
        cudaStreamCreateWithFlags(&s_side, cudaStreamNonBlocking);
        cudaEventCreateWithFlags(&ev_fork, cudaEventDisableTiming);
        cudaEventCreateWithFlags(&ev_join, cudaEventDisableTiming);
    }
} s_side_init;

// ---------------------------------------------------------------------------
// Kernel 0: zero histogram + allocator cursor
// ---------------------------------------------------------------------------
__global__ void k_zero()
{
    int i = blockIdx.x * blockDim.x + threadIdx.x;
    if (i < NODES) g_count[i] = 0;
    if (i == 0) g_cursor = 0;
}

// ---------------------------------------------------------------------------
// Kernel 1: target histogram (only needs idx)
// ---------------------------------------------------------------------------
__global__ __launch_bounds__(256)
void k_hist(const int* __restrict__ idx)
{
    int e = blockIdx.x * blockDim.x + threadIdx.x;
    if (e >= EDGES) return;
    int b   = e / Ee;
    int tgt = idx[(size_t)e * 2 + 1];
    atomicAdd(&g_count[b * Nn + tgt], 1);
}

// ---------------------------------------------------------------------------
// Kernel 2: warp-aggregated segment allocation
// ---------------------------------------------------------------------------
__global__ __launch_bounds__(256)
void k_alloc()
{
    int n    = blockIdx.x * blockDim.x + threadIdx.x;
    int lane = threadIdx.x & 31;

    int c = (n < NODES) ? g_count[n] : 0;

    int s = c;
    #pragma unroll
    for (int off = 1; off < 32; off <<= 1) {
        int v = __shfl_up_sync(0xFFFFFFFFu, s, off);
        if (lane >= off) s += v;
    }
    int total = __shfl_sync(0xFFFFFFFFu, s, 31);

    int base = 0;
    if (lane == 31) base = atomicAdd(&g_cursor, total);
    base = __shfl_sync(0xFFFFFFFFu, base, 31);

    if (n < NODES) {
        int beg = base + s - c;
        g_beg[n] = beg;
        g_pos[n] = beg;
    }
}

// ---------------------------------------------------------------------------
// Kernel 3: projection (side stream). R13 config: fp32 X smem, fp16 output.
// 8 rows x 4 cols per thread, 128-row tile, 2 CTA/SM.
// ---------------------------------------------------------------------------
#define PROJ_ROWS_PER_BLK 128
#define PROJ_BLOCKS (ROWS / PROJ_ROWS_PER_BLK)   /* 1250 */
#define XPITCH 132
#define PROJ_SMEM_BYTES ((128*64 + PROJ_ROWS_PER_BLK*XPITCH) * 4)  /* 100352 */

__global__ __launch_bounds__(256, 2)
void k_project(const float* __restrict__ node,
               const float* __restrict__ hidden,
               const float* __restrict__ Wnh,
               const float* __restrict__ bnh)
{
    extern __shared__ float sm[];
    float* Ws = sm;                  // [128][64]
    float* Xs = sm + 128 * 64;       // [128][XPITCH]

    const int tid  = threadIdx.x;
    const int row0 = blockIdx.x * PROJ_ROWS_PER_BLK;

    #pragma unroll
    for (int i = tid; i < 128 * 64; i += 256) Ws[i] = Wnh[i];

    const float4* node4   = (const float4*)node;
    const float4* hidden4 = (const float4*)hidden;
    #pragma unroll
    for (int i = tid; i < PROJ_ROWS_PER_BLK * 32; i += 256) {
        int r = i >> 5;
        int q = i & 31;
        int grow = row0 + r;
        float4 v;
        int col;
        if (q < 16) { v = __ldg(&node4[(size_t)grow * 16 + q]);          col = q * 4; }
        else        { v = __ldg(&hidden4[(size_t)grow * 16 + (q - 16)]); col = 64 + (q - 16) * 4; }
        *(float4*)&Xs[r * XPITCH + col] = v;
    }
    __syncthreads();

    const int obase = (tid & 15) * 4;   // 16 col-groups * 4 = 64 outputs
    const int rbase = (tid >> 4) * 8;   // 16 row-groups * 8 = 128 rows

    float4 acc[8];
    {
        float4 b = *(const float4*)&bnh[obase];
        #pragma unroll
        for (int r = 0; r < 8; r++) acc[r] = b;
    }

    #pragma unroll 2
    for (int cb = 0; cb < 128; cb += 4) {
        const float4 w0 = *(const float4*)&Ws[(cb + 0) * 64 + obase];
        const float4 w1 = *(const float4*)&Ws[(cb + 1) * 64 + obase];
        const float4 w2 = *(const float4*)&Ws[(cb + 2) * 64 + obase];
        const float4 w3 = *(const float4*)&Ws[(cb + 3) * 64 + obase];
        #pragma unroll
        for (int r = 0; r < 8; r++) {
            const float4 x = *(const float4*)&Xs[(rbase + r) * XPITCH + cb];
            acc[r].x += x.x * w0.x; acc[r].y += x.x * w0.y; acc[r].z += x.x * w0.z; acc[r].w += x.x * w0.w;
            acc[r].x += x.y * w1.x; acc[r].y += x.y * w1.y; acc[r].z += x.y * w1.z; acc[r].w += x.y * w1.w;
            acc[r].x += x.z * w2.x; acc[r].y += x.z * w2.y; acc[r].z += x.z * w2.z; acc[r].w += x.z * w2.w;
            acc[r].x += x.w * w3.x; acc[r].y += x.w * w3.y; acc[r].z += x.w * w3.z; acc[r].w += x.w * w3.w;
        }
    }

    #pragma unroll
    for (int r = 0; r < 8; r++) {
        size_t off = (size_t)(row0 + rbase + r) * 64 + obase;   // half units
        __half2 h0 = __floats2half2_rn(acc[r].x, acc[r].y);
        __half2 h1 = __floats2half2_rn(acc[r].z, acc[r].w);
        uint2 pk;
        pk.x = *(unsigned*)&h0;
        pk.y = *(unsigned*)&h1;
        *(uint2*)(g_nh + off) = pk;    // 8-byte aligned (obase % 4 == 0)
    }
}

// ---------------------------------------------------------------------------
// Kernel 4: per-edge gate + CSR fill. FOUR edges per warp (R13 config);
// ef read with __ldcs (read-once stream, keep g_nh resident in L2).
// ---------------------------------------------------------------------------
__global__ __launch_bounds__(256)
void k_coeff_fill(const float* __restrict__ ef,
                  const float* __restrict__ We,
                  const float* __restrict__ be,
                  const int*   __restrict__ idx)
{
    int wq   = (blockIdx.x * blockDim.x + threadIdx.x) >> 5;   // warp id
    int lane = threadIdx.x & 31;
    int e0   = wq * 4;
    if (e0 >= EDGES) return;

    float wlo = __ldg(&We[lane]);
    float whi = __ldg(&We[lane + 32]);

    float s0, s1, s2, s3;
    {
        const float* r0 = ef + (size_t)(e0 + 0) * 64;
        const float* r1 = ef + (size_t)(e0 + 1) * 64;
        const float* r2 = ef + (size_t)(e0 + 2) * 64;
        const float* r3 = ef + (size_t)(e0 + 3) * 64;
        float a0 = __ldcs(r0 + lane), b0 = __ldcs(r0 + lane + 32);
        float a1 = __ldcs(r1 + lane), b1 = __ldcs(r1 + lane + 32);
        float a2 = __ldcs(r2 + lane), b2 = __ldcs(r2 + lane + 32);
        float a3 = __ldcs(r3 + lane), b3 = __ldcs(r3 + lane + 32);
        s0 = a0 * wlo + b0 * whi;
        s1 = a1 * wlo + b1 * whi;
        s2 = a2 * wlo + b2 * whi;
        s3 = a3 * wlo + b3 * whi;
    }

    #pragma unroll
    for (int off = 16; off > 0; off >>= 1) {
        s0 += __shfl_xor_sync(0xFFFFFFFFu, s0, off);
        s1 += __shfl_xor_sync(0xFFFFFFFFu, s1, off);
        s2 += __shfl_xor_sync(0xFFFFFFFFu, s2, off);
        s3 += __shfl_xor_sync(0xFFFFFFFFu, s3, off);
    }

    if (lane < 4) {
        int e = e0 + lane;
        float s = (lane == 0) ? s0 : (lane == 1) ? s1 : (lane == 2) ? s2 : s3;
        float cf = s + __ldg(&be[0]);
        int2 st  = __ldg((const int2*)idx + e);      // {src, tgt}
        int  b   = e / Ee;
        int  p   = atomicAdd(&g_pos[b * Nn + st.y], 1);
        unsigned long long rec =
            (unsigned long long)(unsigned)st.x |
            ((unsigned long long)__float_as_uint(cf) << 32);
        g_rec[p] = rec;
    }
}

// ---------------------------------------------------------------------------
// Kernel 5: accumulate. TWO warps per node splitting the EDGE LIST (full
// 8-float accumulators each, no metadata duplication); combine via smem +
// 64-thread named barrier per pair. Halves serialized gather-chain length.
// Block = 256 thr = 4 node-pairs; grid exact (NODES/4 blocks).
// ---------------------------------------------------------------------------
__global__ __launch_bounds__(256)
void k_accum(float* __restrict__ out)
{
    __shared__ float comb[4][32][8];   // 16KB: odd-warp partials

    int wid  = threadIdx.x >> 5;       // 0..7
    int lane = threadIdx.x & 31;
    int pair = wid >> 1;               // 0..3
    int sub  = wid & 1;                // 0 = even warp, 1 = odd warp
    int n    = blockIdx.x * 4 + pair;  // node (grid exact, no guard)

    int beg = g_beg[n];
    int cnt = g_count[n];
    int b   = n / Nn;

    // split edges between the two warps of the pair
    int half0 = (cnt + 1) >> 1;
    int myBeg = beg + (sub ? half0 : 0);
    int myCnt = sub ? (cnt - half0) : half0;

    const __half* basep = g_nh + (size_t)b * Nn * 256;

    float a[8];
    #pragma unroll
    for (int i = 0; i < 8; i++) a[i] = 0.f;

    for (int c0 = 0; c0 < myCnt; c0 += 32) {
        int m = myCnt - c0; if (m > 32) m = 32;
        unsigned long long rec = 0;
        if (lane < m) rec = __ldcs(&g_rec[myBeg + c0 + lane]);
        int   rsrc = (int)(unsigned)(rec & 0xFFFFFFFFull);
        float rcf  = __uint_as_float((unsigned)(rec >> 32));

        #pragma unroll 8
        for (int k = 0; k < m; k++) {
            int   sidx = __shfl_sync(0xFFFFFFFFu, rsrc, k);
            float cf   = __shfl_sync(0xFFFFFFFFu, rcf,  k);
            const float4* p = (const float4*)(basep + (size_t)sidx * 256);
            float4 raw = __ldg(p + lane);                      // 8 halves
            const __half2* h2 = (const __half2*)&raw;
            float2 f;
            f = __half22float2(h2[0]); a[0] += cf * f.x; a[1] += cf * f.y;
            f = __half22float2(h2[1]); a[2] += cf * f.x; a[3] += cf * f.y;
            f = __half22float2(h2[2]); a[4] += cf * f.x; a[5] += cf * f.y;
            f = __half22float2(h2[3]); a[6] += cf * f.x; a[7] += cf * f.y;
        }
    }

    // pair combine: odd warp dumps, even warp adds + stores
    if (sub == 1) {
        #pragma unroll
        for (int i = 0; i < 8; i++) comb[pair][lane][i] = a[i];
    }
    asm volatile("bar.sync %0, %1;" :: "r"(pair + 1), "r"(64) : "memory");
    if (sub == 0) {
        #pragma unroll
        for (int i = 0; i < 8; i++) a[i] += comb[pair][lane][i];
        float* t = out + (size_t)n * 256 + lane * 8;
        __stcs((float4*)t,     make_float4(a[0], a[1], a[2], a[3]));
        __stcs((float4*)t + 1, make_float4(a[4], a[5], a[6], a[7]));
    }
}

// ---------------------------------------------------------------------------
// launch graph (edge chain enqueued FIRST so its blocks win SM slots):
//   stream0: zero -> hist -> alloc -> coeff_fill ┐
//   side:    project (dep: graph entry only)     ├-> accum (stream0)
// inputs: node_fts, hidden, edge_fts, W_nh, b_nh, W_e, b_e, edge_indices(i32)
// ---------------------------------------------------------------------------
extern "C" void kernel_launch(void* const* d_in, const int* in_sizes, int n_in,
                              void* d_out, int out_size)
{
    const float* node   = (const float*)d_in[0];
    const float* hidden = (const float*)d_in[1];
    const float* ef     = (const float*)d_in[2];
    const float* Wnh    = (const float*)d_in[3];
    const float* bnh    = (const float*)d_in[4];
    const float* We     = (const float*)d_in[5];
    const float* be     = (const float*)d_in[6];
    const int*   idx    = (const int*)d_in[7];
    float*       out    = (float*)d_out;

    cudaFuncSetAttribute(k_project, cudaFuncAttributeMaxDynamicSharedMemorySize,
                         PROJ_SMEM_BYTES);

    // fork point at graph entry
    cudaEventRecord(ev_fork, 0);
    cudaStreamWaitEvent(s_side, ev_fork, 0);

    // edge chain on the capture stream (enqueued first)
    k_zero<<<(NODES + 255) / 256, 256>>>();
    k_hist<<<(EDGES + 255) / 256, 256>>>(idx);
    k_alloc<<<(NODES + 255) / 256, 256>>>();
    k_coeff_fill<<<(EDGES / 4 + 7) / 8, 256>>>(ef, We, be, idx);

    // projection on side stream (independent branch)
    k_project<<<PROJ_BLOCKS, 256, PROJ_SMEM_BYTES, s_side>>>(node, hidden, Wnh, bnh);
    cudaEventRecord(ev_join, s_side);

    // join: accum needs both g_nh (project) and the CSR records (edge chain)
    cudaStreamWaitEvent(0, ev_join, 0);
    k_accum<<<NODES / 4, 256>>>(out);
}

// round 16
// speedup vs baseline: 1.0800x; 1.0768x over previous
#include <cuda_runtime.h>
#include <cuda_fp16.h>
#include <mma.h>
#include <cstdint>

using namespace nvcuda;

#define Bb 4
#define Nn 10000
#define Ee 160000
#define Mm 4
#define Hh 64
#define OUTd 64
#define Ff 64

#define ROWS (Bb*Nn*Mm)      /* 160000 projected rows, each 128 -> 64 */
#define EDGES (Bb*Ee)        /* 640000 */
#define NODES (Bb*Nn)        /* 40000 target buckets */

// Scratch (allocation-free rule: __device__ globals)
__device__ __half             g_nh[(size_t)ROWS * OUTd];  // 20.5 MB projected (fp16)
__device__ int                g_count[NODES];             // histogram by (b,tgt)
__device__ int                g_beg[NODES];               // segment start
__device__ int                g_pos[NODES];               // fill cursors
__device__ unsigned long long g_rec[EDGES];               // packed {src, coeff}
__device__ int                g_cursor;                   // allocator cursor

// ---------------------------------------------------------------------------
// Side stream + fork/join events (created at load; not device allocations)
// ---------------------------------------------------------------------------
static cudaStream_t s_side;
static cudaEvent_t  ev_fork, ev_join;
static struct SideInit {
    SideInit() {
        cudaStreamCreateWithFlags(&s_side, cudaStreamNonBlocking);
        cudaEventCreateWithFlags(&ev_fork, cudaEventDisableTiming);
        cudaEventCreateWithFlags(&ev_join, cudaEventDisableTiming);
    }
} s_side_init;

// ---------------------------------------------------------------------------
// Kernel 0: zero histogram + allocator cursor
// ---------------------------------------------------------------------------
__global__ void k_zero()
{
    int i = blockIdx.x * blockDim.x + threadIdx.x;
    if (i < NODES) g_count[i] = 0;
    if (i == 0) g_cursor = 0;
}

// ---------------------------------------------------------------------------
// Kernel 1: target histogram (only needs idx)
// ---------------------------------------------------------------------------
__global__ __launch_bounds__(256)
void k_hist(const int* __restrict__ idx)
{
    int e = blockIdx.x * blockDim.x + threadIdx.x;
    if (e >= EDGES) return;
    int b   = e / Ee;
    int tgt = idx[(size_t)e * 2 + 1];
    atomicAdd(&g_count[b * Nn + tgt], 1);
}

// ---------------------------------------------------------------------------
// Kernel 2: warp-aggregated segment allocation
// ---------------------------------------------------------------------------
__global__ __launch_bounds__(256)
void k_alloc()
{
    int n    = blockIdx.x * blockDim.x + threadIdx.x;
    int lane = threadIdx.x & 31;

    int c = (n < NODES) ? g_count[n] : 0;

    int s = c;
    #pragma unroll
    for (int off = 1; off < 32; off <<= 1) {
        int v = __shfl_up_sync(0xFFFFFFFFu, s, off);
        if (lane >= off) s += v;
    }
    int total = __shfl_sync(0xFFFFFFFFu, s, 31);

    int base = 0;
    if (lane == 31) base = atomicAdd(&g_cursor, total);
    base = __shfl_sync(0xFFFFFFFFu, base, 31);

    if (n < NODES) {
        int beg = base + s - c;
        g_beg[n] = beg;
        g_pos[n] = beg;
    }
}

// ---------------------------------------------------------------------------
// Kernel 3: projection via WMMA (fp16 HMMA, fp32 accumulate).
// Block: 64 rows x 64 outs, 256 threads / 8 warps.
// Each warp: two 16x16 C tiles; K-loop of 8 (k=16 per step).
// smem: W fp16 [128][64] (16KB) + union{ X fp16 [64][136] | C fp32 [64][68] }
// (17408B) = 33.8KB static -> ~6 CTA/SM.
// ---------------------------------------------------------------------------
#define PROJ_ROWS_PER_BLK 64
#define PROJ_BLOCKS (ROWS / PROJ_ROWS_PER_BLK)   /* 2500 */
#define XP2 136                                  /* X pitch in halves */
#define CP  68                                   /* C pitch in floats */

__global__ __launch_bounds__(256)
void k_project(const float* __restrict__ node,
               const float* __restrict__ hidden,
               const float* __restrict__ Wnh,
               const float* __restrict__ bnh)
{
    __shared__ __half Wsh[128 * 64];
    __shared__ __align__(16) char buf[PROJ_ROWS_PER_BLK * XP2 * 2];  // 17408B
    __half* Xsh = (__half*)buf;
    float*  Cs  = (float*)buf;

    const int tid  = threadIdx.x;
    const int row0 = blockIdx.x * PROJ_ROWS_PER_BLK;

    // W: fp32 -> fp16 smem (8192 elems)
    #pragma unroll
    for (int i = tid; i < 128 * 64; i += 256)
        Wsh[i] = __float2half(__ldg(&Wnh[i]));

    // X tile: 64 rows x 128 cols fp16 (cols 0-63 node, 64-127 hidden)
    const float4* node4   = (const float4*)node;
    const float4* hidden4 = (const float4*)hidden;
    #pragma unroll
    for (int i = tid; i < PROJ_ROWS_PER_BLK * 32; i += 256) {
        int r = i >> 5;
        int q = i & 31;
        int grow = row0 + r;
        float4 v;
        int col;
        if (q < 16) { v = __ldg(&node4[(size_t)grow * 16 + q]);          col = q * 4; }
        else        { v = __ldg(&hidden4[(size_t)grow * 16 + (q - 16)]); col = 64 + (q - 16) * 4; }
        __half2 h0 = __floats2half2_rn(v.x, v.y);
        __half2 h1 = __floats2half2_rn(v.z, v.w);
        uint2 pk;
        pk.x = *(unsigned*)&h0;
        pk.y = *(unsigned*)&h1;
        *(uint2*)&Xsh[r * XP2 + col] = pk;
    }
    __syncthreads();

    const int warp   = tid >> 5;
    const int tile_r = warp & 3;            // 4 row tiles (16 rows each)
    const int tile_c = (warp >> 2) * 2;     // warps 0-3: cols {0,1}; 4-7: {2,3}

    wmma::fragment<wmma::accumulator, 16, 16, 16, float> c0, c1;
    wmma::fill_fragment(c0, 0.0f);
    wmma::fill_fragment(c1, 0.0f);

    #pragma unroll
    for (int k = 0; k < 8; k++) {
        wmma::fragment<wmma::matrix_a, 16, 16, 16, __half, wmma::row_major> af;
        wmma::fragment<wmma::matrix_b, 16, 16, 16, __half, wmma::row_major> bf0, bf1;
        wmma::load_matrix_sync(af, Xsh + tile_r * 16 * XP2 + k * 16, XP2);
        wmma::load_matrix_sync(bf0, Wsh + (k * 16) * 64 + tile_c * 16, 64);
        wmma::load_matrix_sync(bf1, Wsh + (k * 16) * 64 + (tile_c + 1) * 16, 64);
        wmma::mma_sync(c0, af, bf0, c0);
        wmma::mma_sync(c1, af, bf1, c1);
    }
    __syncthreads();   // X reads done; buf becomes C stage

    wmma::store_matrix_sync(Cs + tile_r * 16 * CP + tile_c * 16, c0, CP, wmma::mem_row_major);
    wmma::store_matrix_sync(Cs + tile_r * 16 * CP + (tile_c + 1) * 16, c1, CP, wmma::mem_row_major);
    __syncthreads();

    // epilogue: add bias, convert to fp16, store (each thread 4 cols x 4 rows)
    #pragma unroll
    for (int i = tid; i < PROJ_ROWS_PER_BLK * 16; i += 256) {
        int r   = i >> 4;
        int col = (i & 15) * 4;
        float4 b4 = *(const float4*)&bnh[col];
        float x0 = Cs[r * CP + col + 0] + b4.x;
        float x1 = Cs[r * CP + col + 1] + b4.y;
        float x2 = Cs[r * CP + col + 2] + b4.z;
        float x3 = Cs[r * CP + col + 3] + b4.w;
        __half2 h0 = __floats2half2_rn(x0, x1);
        __half2 h1 = __floats2half2_rn(x2, x3);
        uint2 pk;
        pk.x = *(unsigned*)&h0;
        pk.y = *(unsigned*)&h1;
        *(uint2*)(g_nh + (size_t)(row0 + r) * 64 + col) = pk;
    }
}

// ---------------------------------------------------------------------------
// Kernel 4: per-edge gate + CSR fill. FOUR edges per warp (R13 config).
// ---------------------------------------------------------------------------
__global__ __launch_bounds__(256)
void k_coeff_fill(const float* __restrict__ ef,
                  const float* __restrict__ We,
                  const float* __restrict__ be,
                  const int*   __restrict__ idx)
{
    int wq   = (blockIdx.x * blockDim.x + threadIdx.x) >> 5;   // warp id
    int lane = threadIdx.x & 31;
    int e0   = wq * 4;
    if (e0 >= EDGES) return;

    float wlo = __ldg(&We[lane]);
    float whi = __ldg(&We[lane + 32]);

    float s0, s1, s2, s3;
    {
        const float* r0 = ef + (size_t)(e0 + 0) * 64;
        const float* r1 = ef + (size_t)(e0 + 1) * 64;
        const float* r2 = ef + (size_t)(e0 + 2) * 64;
        const float* r3 = ef + (size_t)(e0 + 3) * 64;
        float a0 = __ldg(r0 + lane), b0 = __ldg(r0 + lane + 32);
        float a1 = __ldg(r1 + lane), b1 = __ldg(r1 + lane + 32);
        float a2 = __ldg(r2 + lane), b2 = __ldg(r2 + lane + 32);
        float a3 = __ldg(r3 + lane), b3 = __ldg(r3 + lane + 32);
        s0 = a0 * wlo + b0 * whi;
        s1 = a1 * wlo + b1 * whi;
        s2 = a2 * wlo + b2 * whi;
        s3 = a3 * wlo + b3 * whi;
    }

    #pragma unroll
    for (int off = 16; off > 0; off >>= 1) {
        s0 += __shfl_xor_sync(0xFFFFFFFFu, s0, off);
        s1 += __shfl_xor_sync(0xFFFFFFFFu, s1, off);
        s2 += __shfl_xor_sync(0xFFFFFFFFu, s2, off);
        s3 += __shfl_xor_sync(0xFFFFFFFFu, s3, off);
    }

    if (lane < 4) {
        int e = e0 + lane;
        float s = (lane == 0) ? s0 : (lane == 1) ? s1 : (lane == 2) ? s2 : s3;
        float cf = s + __ldg(&be[0]);
        int2 st  = __ldg((const int2*)idx + e);      // {src, tgt}
        int  b   = e / Ee;
        int  p   = atomicAdd(&g_pos[b * Nn + st.y], 1);
        unsigned long long rec =
            (unsigned long long)(unsigned)st.x |
            ((unsigned long long)__float_as_uint(cf) << 32);
        g_rec[p] = rec;
    }
}

// ---------------------------------------------------------------------------
// Kernel 5: accumulate (R13 config — 1 warp/node, fp16 gather, streaming).
// ---------------------------------------------------------------------------
__global__ __launch_bounds__(256)
void k_accum(float* __restrict__ out)
{
    int n    = (blockIdx.x * blockDim.x + threadIdx.x) >> 5;
    int lane = threadIdx.x & 31;
    if (n >= NODES) return;

    int beg = g_beg[n];
    int cnt = g_count[n];
    int b   = n / Nn;

    const __half* basep = g_nh + (size_t)b * Nn * 256;

    float a[8];
    #pragma unroll
    for (int i = 0; i < 8; i++) a[i] = 0.f;

    for (int c0 = 0; c0 < cnt; c0 += 32) {
        int m = cnt - c0; if (m > 32) m = 32;
        unsigned long long rec = 0;
        if (lane < m) rec = __ldcs(&g_rec[beg + c0 + lane]);   // streaming
        int   rsrc = (int)(unsigned)(rec & 0xFFFFFFFFull);
        float rcf  = __uint_as_float((unsigned)(rec >> 32));

        #pragma unroll 8
        for (int k = 0; k < m; k++) {
            int   sidx = __shfl_sync(0xFFFFFFFFu, rsrc, k);
            float cf   = __shfl_sync(0xFFFFFFFFu, rcf,  k);
            const float4* p = (const float4*)(basep + (size_t)sidx * 256);
            float4 raw = __ldg(p + lane);                      // 8 halves
            const __half2* h2 = (const __half2*)&raw;
            float2 f;
            f = __half22float2(h2[0]); a[0] += cf * f.x; a[1] += cf * f.y;
            f = __half22float2(h2[1]); a[2] += cf * f.x; a[3] += cf * f.y;
            f = __half22float2(h2[2]); a[4] += cf * f.x; a[5] += cf * f.y;
            f = __half22float2(h2[3]); a[6] += cf * f.x; a[7] += cf * f.y;
        }
    }

    float* t = out + (size_t)n * 256 + lane * 8;
    __stcs((float4*)t,     make_float4(a[0], a[1], a[2], a[3]));
    __stcs((float4*)t + 1, make_float4(a[4], a[5], a[6], a[7]));
}

// ---------------------------------------------------------------------------
// launch graph:
//   stream0: zero -> hist -> alloc -> coeff_fill ┐
//   side:    project (dep: graph entry only)     ├-> accum (stream0)
// inputs: node_fts, hidden, edge_fts, W_nh, b_nh, W_e, b_e, edge_indices(i32)
// ---------------------------------------------------------------------------
extern "C" void kernel_launch(void* const* d_in, const int* in_sizes, int n_in,
                              void* d_out, int out_size)
{
    const float* node   = (const float*)d_in[0];
    const float* hidden = (const float*)d_in[1];
    const float* ef     = (const float*)d_in[2];
    const float* Wnh    = (const float*)d_in[3];
    const float* bnh    = (const float*)d_in[4];
    const float* We     = (const float*)d_in[5];
    const float* be     = (const float*)d_in[6];
    const int*   idx    = (const int*)d_in[7];
    float*       out    = (float*)d_out;

    // fork point at graph entry
    cudaEventRecord(ev_fork, 0);
    cudaStreamWaitEvent(s_side, ev_fork, 0);

    // edge chain on the capture stream (enqueued first)
    k_zero<<<(NODES + 255) / 256, 256>>>();
    k_hist<<<(EDGES + 255) / 256, 256>>>(idx);
    k_alloc<<<(NODES + 255) / 256, 256>>>();
    k_coeff_fill<<<(EDGES / 4 + 7) / 8, 256>>>(ef, We, be, idx);

    // projection on side stream (independent branch, tensor cores)
    k_project<<<PROJ_BLOCKS, 256, 0, s_side>>>(node, hidden, Wnh, bnh);
    cudaEventRecord(ev_join, s_side);

    // join: accum needs both g_nh (project) and the CSR records (edge chain)
    cudaStreamWaitEvent(0, ev_join, 0);
    k_accum<<<(NODES * 32 + 255) / 256, 256>>>(out);
}